// round 17
// baseline (speedup 1.0000x reference)
#include <cuda_runtime.h>
#include <cuda_bf16.h>
#include <cuda_fp16.h>
#include <math.h>
#include <stdint.h>

#define BB 32
#define NN 128
#define CD 128
#define PP 8128
#define RNDS 3

// ===================== low-level helpers (base ISA only) ======================
__device__ __forceinline__ uint32_t smem_u32(const void* p) {
    uint32_t a;
    asm("{ .reg .u64 t; cvta.to.shared.u64 t, %1; cvt.u32.u64 %0, t; }" : "=r"(a) : "l"(p));
    return a;
}
__device__ __forceinline__ void ldsm4(uint32_t r[4], uint32_t addr) {
    asm volatile("ldmatrix.sync.aligned.m8n8.x4.shared.b16 {%0,%1,%2,%3}, [%4];"
        : "=r"(r[0]), "=r"(r[1]), "=r"(r[2]), "=r"(r[3]) : "r"(addr));
}
__device__ __forceinline__ void mma_bf16(float c[4], const uint32_t a[4],
                                         uint32_t b0, uint32_t b1) {
    asm volatile("mma.sync.aligned.m16n8k16.row.col.f32.bf16.bf16.f32 "
        "{%0,%1,%2,%3}, {%4,%5,%6,%7}, {%8,%9}, {%0,%1,%2,%3};"
        : "+f"(c[0]), "+f"(c[1]), "+f"(c[2]), "+f"(c[3])
        : "r"(a[0]), "r"(a[1]), "r"(a[2]), "r"(a[3]), "r"(b0), "r"(b1));
}
__device__ __forceinline__ void cp16(uint32_t dst, const void* src) {
    asm volatile("cp.async.cg.shared.global [%0], [%1], 16;" :: "r"(dst), "l"(src));
}
#define CP_COMMIT() asm volatile("cp.async.commit_group;" ::: "memory")
#define CP_WAIT1()  asm volatile("cp.async.wait_group 1;" ::: "memory")
#define CP_WAIT0()  asm volatile("cp.async.wait_group 0;" ::: "memory")

__device__ __forceinline__ void split_pair(float x, float y, uint32_t& hi, uint32_t& lo) {
    __nv_bfloat16 hx = __float2bfloat16(x), hy = __float2bfloat16(y);
    float rx = x - __bfloat162float(hx), ry = y - __bfloat162float(hy);
    __nv_bfloat16 lx = __float2bfloat16(rx), ly = __float2bfloat16(ry);
    hi = (uint32_t)*(uint16_t*)&hx | ((uint32_t)*(uint16_t*)&hy << 16);
    lo = (uint32_t)*(uint16_t*)&lx | ((uint32_t)*(uint16_t*)&ly << 16);
}
template<int SH>
__device__ __host__ __forceinline__ uint32_t swz(int r, int k) {
    return ((uint32_t)r << SH) + ((uint32_t)(((k >> 3) ^ (r & 7))) << 4) + ((uint32_t)(k & 7) << 1);
}

// ---- GEMM: warp = M16 x N(8*NTP), 3-pass split, ILP-reordered ----
template<int SHA, int SHB, int NKS, int NTP>
__device__ __forceinline__ void gemm_split2(uint32_t sb, uint32_t offA, uint32_t offAlo,
                                            uint32_t bHi, uint32_t bLo,
                                            int mbase, int ks0, int lane, float acc[][4]) {
    int arow = mbase + (lane & 7) + (((lane >> 3) & 1) << 3);
    uint32_t aBase   = sb + offA + ((uint32_t)arow << SHA);
    uint32_t aBaseLo = sb + offAlo + ((uint32_t)arow << SHA);
    int a7 = arow & 7, agrp = (lane >> 4) & 1;
    int brow0 = (lane & 7) + ((lane >> 4) << 3);
    int b7 = lane & 7, bkb = (lane >> 3) & 1;
#pragma unroll
    for (int ks = 0; ks < NKS; ++ks) {
        uint32_t ak = (uint32_t)(((((ks0 + ks) << 1) | agrp) ^ a7) << 4);
        uint32_t Ah[4], Al[4];
        ldsm4(Ah, aBase + ak);
        ldsm4(Al, aBaseLo + ak);
        uint32_t bk = (uint32_t)((((ks << 1) | bkb) ^ b7) << 4);
#pragma unroll
        for (int tp = 0; tp < NTP; ++tp) {
            uint32_t brow = (uint32_t)(brow0 + (tp << 4)) << SHB;
            uint32_t Bh[4], Bl[4];
            ldsm4(Bh, bHi + brow + bk);
            ldsm4(Bl, bLo + brow + bk);
            mma_bf16(acc[2*tp],     Ah, Bh[0], Bh[1]);
            mma_bf16(acc[2*tp + 1], Ah, Bh[2], Bh[3]);
            mma_bf16(acc[2*tp],     Al, Bh[0], Bh[1]);
            mma_bf16(acc[2*tp + 1], Al, Bh[2], Bh[3]);
            mma_bf16(acc[2*tp],     Ah, Bl[0], Bl[1]);
            mma_bf16(acc[2*tp + 1], Ah, Bl[2], Bl[3]);
        }
    }
}

// ---- edge GEMM: warp = M32 x N32 (2 row-tiles, NTP=2), 3-pass split ----
template<int SHA, int SHB, int NKS>
__device__ __forceinline__ void gemm_split22(uint32_t sb, uint32_t offA, uint32_t offAlo,
                                             uint32_t bHi, uint32_t bLo,
                                             int rbase, int ncol0, int ks0, int lane,
                                             float acc[][4]) {
    int arow = rbase + (lane & 7) + (((lane >> 3) & 1) << 3);
    uint32_t a0h = sb + offA   + ((uint32_t)arow << SHA);
    uint32_t a0l = sb + offAlo + ((uint32_t)arow << SHA);
    uint32_t a1h = a0h + (16u << SHA);
    uint32_t a1l = a0l + (16u << SHA);
    int a7 = lane & 7, agrp = (lane >> 4) & 1;
    int brow0 = (lane & 7) + ((lane >> 4) << 3) + ncol0;
    int b7 = lane & 7, bkb = (lane >> 3) & 1;
#pragma unroll
    for (int ks = 0; ks < NKS; ++ks) {
        uint32_t ak = (uint32_t)(((((ks0 + ks) << 1) | agrp) ^ a7) << 4);
        uint32_t A0h[4], A0l[4], A1h[4], A1l[4];
        ldsm4(A0h, a0h + ak); ldsm4(A0l, a0l + ak);
        ldsm4(A1h, a1h + ak); ldsm4(A1l, a1l + ak);
        uint32_t bk = (uint32_t)((((ks << 1) | bkb) ^ b7) << 4);
#pragma unroll
        for (int tp = 0; tp < 2; ++tp) {
            uint32_t brow = (uint32_t)(brow0 + (tp << 4)) << SHB;
            uint32_t Bh[4], Bl[4];
            ldsm4(Bh, bHi + brow + bk);
            ldsm4(Bl, bLo + brow + bk);
            mma_bf16(acc[tp*2],       A0h, Bh[0], Bh[1]);
            mma_bf16(acc[tp*2 + 1],   A0h, Bh[2], Bh[3]);
            mma_bf16(acc[4+tp*2],     A1h, Bh[0], Bh[1]);
            mma_bf16(acc[4+tp*2 + 1], A1h, Bh[2], Bh[3]);
            mma_bf16(acc[tp*2],       A0l, Bh[0], Bh[1]);
            mma_bf16(acc[tp*2 + 1],   A0l, Bh[2], Bh[3]);
            mma_bf16(acc[4+tp*2],     A1l, Bh[0], Bh[1]);
            mma_bf16(acc[4+tp*2 + 1], A1l, Bh[2], Bh[3]);
            mma_bf16(acc[tp*2],       A0h, Bl[0], Bl[1]);
            mma_bf16(acc[tp*2 + 1],   A0h, Bl[2], Bl[3]);
            mma_bf16(acc[4+tp*2],     A1h, Bl[0], Bl[1]);
            mma_bf16(acc[4+tp*2 + 1], A1h, Bl[2], Bl[3]);
        }
    }
}

// ===================== persistent device scratch ==============================
__device__ unsigned short g_ebf[(size_t)BB*NN*32768];
__device__ uint32_t g_mbuf[(size_t)BB*NN*NN*CD/2];
__device__ float g_h   [BB*NN*CD];
__device__ float g_hp  [BB*NN*512];
__device__ float g_ms  [BB*NN*CD];
__device__ float g_gi  [BB*NN*384];
__device__ float g_gh  [BB*NN*384];
__device__ int   g_iu  [PP];
__device__ int   g_ju  [PP];
__device__ unsigned short g_wt [4*32768];
__device__ unsigned short g_wr [4*32768];
__device__ unsigned short g_whp[4*32768];
__device__ unsigned short g_wgi[2*98304];

// ===================== prep kernels ===========================================
__global__ void k_prep_w(const float* __restrict__ Wl_e, const float* __restrict__ Wm_e,
                         const float* __restrict__ Wu_e, const float* __restrict__ Wu_m,
                         const float* __restrict__ Wl_w, const float* __restrict__ Wl_v,
                         const float* __restrict__ Wm_w, const float* __restrict__ Wm_v,
                         const float* __restrict__ W_ih, const float* __restrict__ W_hh) {
    int idx = blockIdx.x * blockDim.x + threadIdx.x;
    if (idx < 65536) {
        int m = idx >> 14, r = idx & 16383, n = r >> 7, k = r & 127;
        const float* W = (m == 0) ? Wl_e : (m == 1) ? Wm_e : (m == 2) ? Wu_e : Wu_m;
        float v = W[k*128 + n];
        __nv_bfloat16 hi = __float2bfloat16(v);
        __nv_bfloat16 lo = __float2bfloat16(v - __bfloat162float(hi));
        uint32_t o = (uint32_t)m*65536u + (uint32_t)(k >> 6)*32768u + swz<7>(n, k & 63);
        *(__nv_bfloat16*)((char*)g_wt + o) = hi;
        *(__nv_bfloat16*)((char*)g_wt + o + 16384) = lo;
    } else if (idx < 131072) {
        int r = idx - 65536;
        int m = r >> 14, e = r & 16383, n = e >> 7, k = e & 127;
        const float* W = (m == 0) ? Wl_w : (m == 1) ? Wl_v : (m == 2) ? Wm_w : Wm_v;
        float v = W[k*128 + n];
        __nv_bfloat16 hi = __float2bfloat16(v);
        __nv_bfloat16 lo = __float2bfloat16(v - __bfloat162float(hi));
        uint32_t o = (uint32_t)((m << 1) | (n >> 6))*32768u + swz<8>(n & 63, k);
        *(__nv_bfloat16*)((char*)g_whp + o) = hi;
        *(__nv_bfloat16*)((char*)g_whp + o + 16384) = lo;
    } else if (idx < 229376) {
        int r = idx - 131072;
        int m = r / 49152, e = r % 49152, n = e >> 7, k = e & 127;
        const float* W = m ? W_hh : W_ih;
        float v = W[k*384 + n];
        __nv_bfloat16 hi = __float2bfloat16(v);
        __nv_bfloat16 lo = __float2bfloat16(v - __bfloat162float(hi));
        uint32_t o = (uint32_t)m*196608u + (uint32_t)(n >> 6)*32768u + swz<8>(n & 63, k);
        *(__nv_bfloat16*)((char*)g_wgi + o) = hi;
        *(__nv_bfloat16*)((char*)g_wgi + o + 16384) = lo;
    }
}

__global__ void k_prep_wr(const float* __restrict__ Wr1) {
    int idx = blockIdx.x * blockDim.x + threadIdx.x;
    if (idx < NN*NN) {
        int i = idx / NN, j = idx % NN;
        if (j > i) {
            int p = i*(NN-1) - i*(i-1)/2 + (j - i - 1);
            g_iu[p] = i; g_ju[p] = j;
        }
    }
    if (idx >= 65536) return;
    int n = idx >> 8, k = idx & 255;
    float v = Wr1[k*256 + n];
    __nv_bfloat16 hi = __float2bfloat16(v);
    __nv_bfloat16 lo = __float2bfloat16(v - __bfloat162float(hi));
    uint32_t o = (uint32_t)(n >> 6)*65536u + (uint32_t)(k >> 7)*32768u + swz<8>(n & 63, k & 127);
    *(__nv_bfloat16*)((char*)g_wr + o) = hi;
    *(__nv_bfloat16*)((char*)g_wr + o + 16384) = lo;
}

// ===================== HMMA node GEMMs (chunk-parallel, occ 2) ================
#define H2_AHI 0u
#define H2_ALO 32768u
#define H2_W   65536u
#define H2_SMEM 98304

__global__ __launch_bounds__(256, 2)
void k_rgemm_hp(const float* __restrict__ nf, const float* __restrict__ bl1,
                const float* __restrict__ bm, int first) {
    extern __shared__ char smem[];
    uint32_t sb = smem_u32(smem);
    int tid = threadIdx.x, warp = tid >> 5, l = tid & 31, q = l & 3;
    int row0 = blockIdx.x * 128;
    int c = blockIdx.y;
    const float* A = first ? nf : g_h;
    const char* wsrc = (const char*)g_whp + (size_t)c*32768;

#pragma unroll
    for (int t = 0; t < 8; ++t)
        cp16(sb + H2_W + (uint32_t)(tid + t*256)*16u, wsrc + (size_t)(tid + t*256)*16);
    CP_COMMIT();

    for (int t = tid; t < 4096; t += 256) {
        float4 v = ((const float4*)(A + (size_t)row0*128))[t];
        if (first && c == 0) ((float4*)(g_h + (size_t)row0*128))[t] = v;
        int r = t >> 5, k0 = (t & 31) << 2;
        uint32_t h01, l01, h23, l23;
        split_pair(v.x, v.y, h01, l01);
        split_pair(v.z, v.w, h23, l23);
        uint32_t o = swz<8>(r, k0);
        *(uint2*)(smem + H2_AHI + o) = make_uint2(h01, h23);
        *(uint2*)(smem + H2_ALO + o) = make_uint2(l01, l23);
    }
    CP_WAIT0();
    __syncthreads();

    int rA = row0 + (warp << 4) + (l >> 2), rB = rA + 8;
    float acc[8][4];
#pragma unroll
    for (int t = 0; t < 8; ++t)
#pragma unroll
        for (int e = 0; e < 4; ++e) acc[t][e] = 0.f;
    gemm_split2<8,8,8,4>(sb, H2_AHI, H2_ALO, sb + H2_W, sb + H2_W + 16384u, warp << 4, 0, l, acc);

    int m = c >> 1;
    const float* bias = (m == 0) ? bl1 : (m == 2) ? bm : nullptr;
    int cIn = (c & 1) * 64;
    int cOut = (m << 7) + cIn;
#pragma unroll
    for (int t = 0; t < 8; ++t) {
        int col = (t << 3) + (q << 1);
        float bx = 0.f, by = 0.f;
        if (bias) { bx = bias[cIn + col]; by = bias[cIn + col + 1]; }
        *(float2*)&g_hp[(size_t)rA*512 + cOut + col] = make_float2(acc[t][0] + bx, acc[t][1] + by);
        *(float2*)&g_hp[(size_t)rB*512 + cOut + col] = make_float2(acc[t][2] + bx, acc[t][3] + by);
    }
}

__global__ __launch_bounds__(256, 2)
void k_rgemm_gig(const float* __restrict__ bih, const float* __restrict__ bhh) {
    extern __shared__ char smem[];
    uint32_t sb = smem_u32(smem);
    int tid = threadIdx.x, warp = tid >> 5, l = tid & 31, q = l & 3;
    int row0 = blockIdx.x * 128;
    int c = blockIdx.y;
    int z = blockIdx.z;
    const float* A = z ? g_h : g_ms;
    const float* bias = z ? bhh : bih;
    float* C = z ? g_gh : g_gi;
    const char* wsrc = (const char*)g_wgi + (size_t)z*196608 + (size_t)c*32768;

#pragma unroll
    for (int t = 0; t < 8; ++t)
        cp16(sb + H2_W + (uint32_t)(tid + t*256)*16u, wsrc + (size_t)(tid + t*256)*16);
    CP_COMMIT();

    for (int t = tid; t < 4096; t += 256) {
        float4 v = ((const float4*)(A + (size_t)row0*128))[t];
        int r = t >> 5, k0 = (t & 31) << 2;
        uint32_t h01, l01, h23, l23;
        split_pair(v.x, v.y, h01, l01);
        split_pair(v.z, v.w, h23, l23);
        uint32_t o = swz<8>(r, k0);
        *(uint2*)(smem + H2_AHI + o) = make_uint2(h01, h23);
        *(uint2*)(smem + H2_ALO + o) = make_uint2(l01, l23);
    }
    CP_WAIT0();
    __syncthreads();

    int rA = row0 + (warp << 4) + (l >> 2), rB = rA + 8;
    float acc[8][4];
#pragma unroll
    for (int t = 0; t < 8; ++t)
#pragma unroll
        for (int e = 0; e < 4; ++e) acc[t][e] = 0.f;
    gemm_split2<8,8,8,4>(sb, H2_AHI, H2_ALO, sb + H2_W, sb + H2_W + 16384u, warp << 4, 0, l, acc);

    int cOut = c * 64;
#pragma unroll
    for (int t = 0; t < 8; ++t) {
        int col = (t << 3) + (q << 1);
        float bx = bias[cOut + col], by = bias[cOut + col + 1];
        *(float2*)&C[(size_t)rA*384 + cOut + col] = make_float2(acc[t][0] + bx, acc[t][1] + by);
        *(float2*)&C[(size_t)rB*384 + cOut + col] = make_float2(acc[t][2] + bx, acc[t][3] + by);
    }
}

// ===================== fused edge kernel: 256 thr, M32xN32 warps ==============
#define EHI 0u
#define ELO 16384u
#define EW0 32768u
#define EW1 65536u
#define ESCR 98304u
#define EDGE_SMEM 99328

__global__ __launch_bounds__(256, 2)
void k_edge_mma(const float* __restrict__ wl2, const float* __restrict__ bl2,
                const float* __restrict__ bu,  const int* __restrict__ ev,
                const int* __restrict__ eids,  const float* __restrict__ emb, int first) {
    extern __shared__ char smem[];
    uint32_t sb = smem_u32(smem);
    int tid = threadIdx.x, warp = tid >> 5, l = tid & 31, q = l & 3;
    int cta = blockIdx.x;
    int bi = cta >> 1, jh = cta & 1;
    int b = bi >> 7, i = bi & 127;
    int vn = ev[b];
    bool pmi = (i < vn);
    bool ctaValid = pmi && (jh*64 < vn);
    const char* wsrc = (const char*)g_wt;
    char* eb = (char*)g_ebf + (size_t)bi*65536;

    if (!ctaValid) {
        if (first) {
            for (int t = tid; t < 2048; t += 256) {
                int lr = t >> 5, c4 = t & 31;
                int gj = jh*64 + lr;
                int id = eids[((size_t)bi << 7) + gj];
                float4 v = ((const float4*)emb)[id*32 + c4];
                uint32_t h01, l01, h23, l23;
                split_pair(v.x, v.y, h01, l01);
                split_pair(v.z, v.w, h23, l23);
                uint32_t go = swz<8>(gj, c4 << 2);
                *(uint2*)(eb + go)          = make_uint2(h01, h23);
                *(uint2*)(eb + 32768u + go) = make_uint2(l01, l23);
            }
        }
        return;
    }

    const int mats[8] = {0, 0, 2, 2, 1, 1, 3, 3};

    if (!first) {
#pragma unroll
        for (int t = 0; t < 4; ++t)
            cp16(sb + EHI + (uint32_t)(tid + t*256)*16u,
                 eb + (uint32_t)jh*16384u + (size_t)(tid + t*256)*16);
#pragma unroll
        for (int t = 0; t < 4; ++t)
            cp16(sb + ELO + (uint32_t)(tid + t*256)*16u,
                 eb + 32768u + (uint32_t)jh*16384u + (size_t)(tid + t*256)*16);
        CP_COMMIT();
    }
#pragma unroll
    for (int t = 0; t < 8; ++t)
        cp16(sb + EW0 + (uint32_t)(tid + t*256)*16u, wsrc + (size_t)(tid + t*256)*16);
    CP_COMMIT();
#pragma unroll
    for (int t = 0; t < 8; ++t)
        cp16(sb + EW1 + (uint32_t)(tid + t*256)*16u, wsrc + 32768 + (size_t)(tid + t*256)*16);
    CP_COMMIT();

    if (first) {
        int* sEid = (int*)(smem + ESCR);
        if (tid < 64) sEid[tid] = eids[((size_t)bi << 7) + jh*64 + tid];
        __syncthreads();
        for (int t = tid; t < 2048; t += 256) {
            int lr = t >> 5, c4 = t & 31;
            int id = sEid[lr];
            float4 v = ((const float4*)emb)[id*32 + c4];
            uint32_t h01, l01, h23, l23;
            split_pair(v.x, v.y, h01, l01);
            split_pair(v.z, v.w, h23, l23);
            uint32_t o = swz<8>(lr, c4 << 2);
            *(uint2*)(smem + EHI + o) = make_uint2(h01, h23);
            *(uint2*)(smem + ELO + o) = make_uint2(l01, l23);
            int gj = jh*64 + lr;
            if (gj >= vn) {
                uint32_t go = swz<8>(gj, c4 << 2);
                *(uint2*)(eb + go)          = make_uint2(h01, h23);
                *(uint2*)(eb + 32768u + go) = make_uint2(l01, l23);
            }
        }
    }

    int wg = warp >> 2, nq = warp & 3;
    int rbase = wg << 5, ncol0 = nq << 5;
    int r0 = l >> 2;
    int Ls[4] = { rbase + r0, rbase + r0 + 8, rbase + r0 + 16, rbase + r0 + 24 };
    bool vs[4];
#pragma unroll
    for (int k2 = 0; k2 < 4; ++k2) vs[k2] = (jh*64 + Ls[k2] < vn);
    bool warpLive = (jh*64 + rbase) < vn;     // all 32 rows of this wg dead otherwise
    const float* hpi = g_hp + (size_t)bi*512;
    float acc[8][4], accU[8][4];
    float sig[4] = {0.f, 0.f, 0.f, 0.f};

#pragma unroll
    for (int c = 0; c < 8; ++c) {
        if (c == 7) { CP_WAIT0(); } else { CP_WAIT1(); }
        __syncthreads();
        if (c == 0 || c == 4) {
#pragma unroll
            for (int t = 0; t < 8; ++t)
#pragma unroll
                for (int e = 0; e < 4; ++e) acc[t][e] = 0.f;
        }
        if (c == 2) {
#pragma unroll
            for (int t = 0; t < 8; ++t)
#pragma unroll
                for (int e = 0; e < 4; ++e) accU[t][e] = 0.f;
        }
        if (warpLive) {
            uint32_t wb = sb + EW0 + (uint32_t)(c & 1)*32768u;
            float (*tg)[4] = (c == 2 || c == 3 || c >= 6) ? accU : acc;
            gemm_split22<8,7,4>(sb, EHI, ELO, wb, wb + 16384u, rbase, ncol0, (c & 1)*4, l, tg);
        }
        __syncthreads();
        if (c + 2 < 8) {
            uint32_t db = sb + EW0 + (uint32_t)(c & 1)*32768u;
            const char* src = wsrc + (size_t)mats[c + 2]*65536 + (size_t)(c & 1)*32768;
#pragma unroll
            for (int t = 0; t < 8; ++t)
                cp16(db + (uint32_t)(tid + t*256)*16u, src + (size_t)(tid + t*256)*16);
            CP_COMMIT();
        }

        if (c == 1) {
            if (warpLive) {
                float par[4] = {0.f, 0.f, 0.f, 0.f};
#pragma unroll
                for (int rt = 0; rt < 2; ++rt) {
                    const float* hvA = g_hp + ((size_t)(b*NN + jh*64 + Ls[rt*2]))*512 + 128;
                    const float* hvB = g_hp + ((size_t)(b*NN + jh*64 + Ls[rt*2+1]))*512 + 128;
#pragma unroll
                    for (int nt = 0; nt < 4; ++nt) {
                        int cc = ncol0 + (nt << 3) + (q << 1);
                        float2 hw = *(const float2*)(hpi + cc);
                        float2 w2 = *(const float2*)(wl2 + cc);
                        float2 vA = *(const float2*)(hvA + cc);
                        float2 vB = *(const float2*)(hvB + cc);
                        const float* a = acc[rt*4 + nt];
                        par[rt*2]   = fmaf(fmaxf(a[0] + hw.x + vA.x, 0.f), w2.x, par[rt*2]);
                        par[rt*2]   = fmaf(fmaxf(a[1] + hw.y + vA.y, 0.f), w2.y, par[rt*2]);
                        par[rt*2+1] = fmaf(fmaxf(a[2] + hw.x + vB.x, 0.f), w2.x, par[rt*2+1]);
                        par[rt*2+1] = fmaf(fmaxf(a[3] + hw.y + vB.y, 0.f), w2.y, par[rt*2+1]);
                    }
                }
#pragma unroll
                for (int k2 = 0; k2 < 4; ++k2) {
                    par[k2] += __shfl_xor_sync(~0u, par[k2], 1);
                    par[k2] += __shfl_xor_sync(~0u, par[k2], 2);
                }
                float* sPart = (float*)(smem + ESCR);
                if (q == 0) {
#pragma unroll
                    for (int k2 = 0; k2 < 4; ++k2) sPart[Ls[k2]*4 + nq] = par[k2];
                }
            }
            __syncthreads();
            if (warpLive) {
                float bl2v = bl2[0];
#pragma unroll
                for (int k2 = 0; k2 < 4; ++k2) {
                    const float* sp = (const float*)(smem + ESCR) + Ls[k2]*4;
                    float adj = sp[0] + sp[1] + sp[2] + sp[3] + bl2v;
                    sig[k2] = vs[k2] ? (1.f/(1.f + expf(-adj))) : 0.f;
                }
            }
        }
        if (c == 5 && warpLive) {
            uint32_t* mbu = g_mbuf + (size_t)bi*NN*(CD/2);
#pragma unroll
            for (int rt = 0; rt < 2; ++rt) {
                int RA = Ls[rt*2], RB = Ls[rt*2+1];
                int gA = jh*64 + RA, gB = jh*64 + RB;
                const float* hvA = g_hp + ((size_t)(b*NN + gA))*512 + 384;
                const float* hvB = g_hp + ((size_t)(b*NN + gB))*512 + 384;
#pragma unroll
                for (int nt = 0; nt < 4; ++nt) {
                    int cc = ncol0 + (nt << 3) + (q << 1);
                    float2 hw = *(const float2*)(hpi + 256 + cc);
                    float2 vA = *(const float2*)(hvA + cc);
                    float2 vB = *(const float2*)(hvB + cc);
                    const float* a = acc[rt*4 + nt];
                    float mA0 = fmaxf(a[0] + hw.x + vA.x, 0.f) * sig[rt*2];
                    float mA1 = fmaxf(a[1] + hw.y + vA.y, 0.f) * sig[rt*2];
                    float mB0 = fmaxf(a[2] + hw.x + vB.x, 0.f) * sig[rt*2+1];
                    float mB1 = fmaxf(a[3] + hw.y + vB.y, 0.f) * sig[rt*2+1];
                    *(__half2*)&mbu[gA*(CD/2) + (cc >> 1)] = __floats2half2_rn(mA0, mA1);
                    *(__half2*)&mbu[gB*(CD/2) + (cc >> 1)] = __floats2half2_rn(mB0, mB1);
                    uint32_t hA, lA, hB, lB;
                    split_pair(mA0, mA1, hA, lA);
                    split_pair(mB0, mB1, hB, lB);
                    uint32_t oA = swz<8>(RA, cc), oB = swz<8>(RB, cc);
                    *(uint32_t*)(smem + EHI + oA) = hA;
                    *(uint32_t*)(smem + ELO + oA) = lA;
                    *(uint32_t*)(smem + EHI + oB) = hB;
                    *(uint32_t*)(smem + ELO + oB) = lB;
                }
            }
        }
    }

    if (warpLive) {
#pragma unroll
        for (int rt = 0; rt < 2; ++rt) {
            int gA = jh*64 + Ls[rt*2], gB = jh*64 + Ls[rt*2+1];
#pragma unroll
            for (int nt = 0; nt < 4; ++nt) {
                int cc = ncol0 + (nt << 3) + (q << 1);
                float2 b2 = *(const float2*)(bu + cc);
                const float* a = accU[rt*4 + nt];
                if (vs[rt*2]) {
                    uint32_t h, lo2;
                    split_pair(fmaxf(a[0] + b2.x, 0.f), fmaxf(a[1] + b2.y, 0.f), h, lo2);
                    uint32_t o = swz<8>(gA, cc);
                    *(uint32_t*)(eb + o) = h;
                    *(uint32_t*)(eb + 32768u + o) = lo2;
                }
                if (vs[rt*2+1]) {
                    uint32_t h, lo2;
                    split_pair(fmaxf(a[2] + b2.x, 0.f), fmaxf(a[3] + b2.y, 0.f), h, lo2);
                    uint32_t o = swz<8>(gB, cc);
                    *(uint32_t*)(eb + o) = h;
                    *(uint32_t*)(eb + 32768u + o) = lo2;
                }
            }
        }
    }
}

// ===================== ms reduce (packed fp16, i < vn) / GRU ==================
__global__ void k_reduce_ms(const int* __restrict__ ev) {
    int t = blockIdx.x * blockDim.x + threadIdx.x;
    if (t >= BB*NN*CD/4) return;
    int b   = t / (NN*CD/4);
    int jk4 = t % (NN*CD/4);
    int vn = ev[b];
    const uint2* base = (const uint2*)g_mbuf + (size_t)b*NN*(NN*CD/4) + jk4;
    float4 s = make_float4(0.f, 0.f, 0.f, 0.f);
    for (int i = 0; i < vn; ++i) {
        uint2 u = base[(size_t)i*(NN*CD/4)];
        float2 p0 = __half22float2(*(__half2*)&u.x);
        float2 p1 = __half22float2(*(__half2*)&u.y);
        s.x += p0.x; s.y += p0.y; s.z += p1.x; s.w += p1.y;
    }
    ((float4*)g_ms)[t] = s;
}

__global__ void k_gru(const int* __restrict__ ev) {
    int t = blockIdx.x * blockDim.x + threadIdx.x;
    if (t >= BB*NN*CD) return;
    int row = t / CD, c = t % CD;
    int b = row / NN, n = row % NN;
    if (n >= ev[b]) return;
    const float* gi = g_gi + (size_t)row*384;
    const float* gh = g_gh + (size_t)row*384;
    float ir = gi[c], iz = gi[CD+c], in = gi[2*CD+c];
    float hr = gh[c], hz = gh[CD+c], hn = gh[2*CD+c];
    float r  = 1.f/(1.f + expf(-(ir+hr)));
    float z  = 1.f/(1.f + expf(-(iz+hz)));
    float nn = tanhf(in + r*hn);
    float hold = g_h[t];
    g_h[t] = (1.f - z)*nn + z*hold;
}

// ===================== readout (HMMA, 64-pair blocks, occ 2) ==================
#define R2_AHI 0u
#define R2_ALO 32768u
#define R2_W0  65536u
#define R2_W1  81920u
#define R2_SMEM 98304

__global__ __launch_bounds__(128, 2)
void k_readout_mma(const float* __restrict__ br1, const float* __restrict__ Wr2g,
                   const float* __restrict__ br2, const int* __restrict__ ev,
                   float* __restrict__ out) {
    extern __shared__ char smem[];
    __shared__ float sWr2[2560];
    __shared__ float sBr1[256];
    uint32_t sb = smem_u32(smem);
    int tid = threadIdx.x, warp = tid >> 5, l = tid & 31, q = l & 3;
    int b = blockIdx.y, p0 = blockIdx.x * 64;
    int vn = ev[b];
    const char* wsrc = (const char*)g_wr;

    int myValid = 0;
    if (tid < 64) { if (g_ju[p0 + tid] < vn) myValid = 1; }
    if (!__syncthreads_or(myValid)) return;

#pragma unroll
    for (int t = 0; t < 4; ++t) {
        cp16(sb + R2_W0 + (uint32_t)(tid + t*128)*16u, wsrc + (size_t)(tid + t*128)*16);
        cp16(sb + R2_W0 + 8192u + (uint32_t)(tid + t*128)*16u, wsrc + 16384 + (size_t)(tid + t*128)*16);
    }
    CP_COMMIT();
#pragma unroll
    for (int t = 0; t < 4; ++t) {
        cp16(sb + R2_W1 + (uint32_t)(tid + t*128)*16u, wsrc + 32768 + (size_t)(tid + t*128)*16);
        cp16(sb + R2_W1 + 8192u + (uint32_t)(tid + t*128)*16u, wsrc + 32768 + 16384 + (size_t)(tid + t*128)*16);
    }
    CP_COMMIT();

    for (int t = tid; t < 2560; t += 128) sWr2[t] = Wr2g[t];
    for (int t = tid; t < 256; t += 128) sBr1[t] = br1[t];

    for (int t = tid; t < 4096; t += 128) {
        int lp = t >> 6, c = (t & 63) << 2;
        int p = p0 + lp;
        int iu = g_iu[p], ju = g_ju[p];
        const char* base; uint32_t o;
        if (c < 128) {
            base = (const char*)g_ebf + (size_t)(b*NN + iu)*65536;
            o = swz<8>(ju, c);
        } else {
            base = (const char*)g_ebf + (size_t)(b*NN + ju)*65536;
            o = swz<8>(iu, c - 128);
        }
        uint2 hi = *(const uint2*)(base + o);
        uint2 lo = *(const uint2*)(base + 32768 + o);
        uint32_t off = swz<9>(lp, c);
        *(uint2*)(smem + R2_AHI + off) = hi;
        *(uint2*)(smem + R2_ALO + off) = lo;
    }

    int rA = (warp << 4) + (l >> 2), rB = rA + 8;
    float outA[10], outB[10];
#pragma unroll
    for (int t5 = 0; t5 < 10; ++t5) { outA[t5] = 0.f; outB[t5] = 0.f; }
    float acc[4][4];

#pragma unroll
    for (int c2 = 0; c2 < 16; ++c2) {
        if (c2 == 15) { CP_WAIT0(); } else { CP_WAIT1(); }
        __syncthreads();
        if ((c2 & 1) == 0) {
#pragma unroll
            for (int t = 0; t < 4; ++t)
#pragma unroll
                for (int e = 0; e < 4; ++e) acc[t][e] = 0.f;
        }
        uint32_t wb = sb + R2_W0 + (uint32_t)(c2 & 1)*16384u;
        gemm_split2<9,8,8,2>(sb, R2_AHI, R2_ALO, wb, wb + 8192u, warp << 4, (c2 & 1)*8, l, acc);
        __syncthreads();
        if (c2 + 2 < 16) {
            int nc = c2 + 2;
            int g = nc >> 1, cc = g >> 1, nh = g & 1, half = nc & 1;
            const char* srcHi = wsrc + (size_t)cc*65536 + (size_t)half*32768 + (size_t)nh*8192;
            uint32_t db = sb + R2_W0 + (uint32_t)(c2 & 1)*16384u;
#pragma unroll
            for (int t = 0; t < 4; ++t) {
                cp16(db + (uint32_t)(tid + t*128)*16u, srcHi + (size_t)(tid + t*128)*16);
                cp16(db + 8192u + (uint32_t)(tid + t*128)*16u, srcHi + 16384 + (size_t)(tid + t*128)*16);
            }
            CP_COMMIT();
        }
        if (c2 & 1) {
            int g = c2 >> 1;
#pragma unroll
            for (int t = 0; t < 4; ++t) {
                int n0 = (g << 5) + (t << 3) + (q << 1);
#pragma unroll
                for (int e = 0; e < 4; ++e) {
                    int n = n0 + (e & 1);
                    float h = fmaxf(acc[t][e] + sBr1[n], 0.f);
                    float* o = (e < 2) ? outA : outB;
                    const float* w = sWr2 + n*10;
#pragma unroll
                    for (int t5 = 0; t5 < 10; ++t5) o[t5] = fmaf(h, w[t5], o[t5]);
                }
            }
        }
    }

#pragma unroll
    for (int t5 = 0; t5 < 10; ++t5) {
        outA[t5] += __shfl_xor_sync(~0u, outA[t5], 1);
        outA[t5] += __shfl_xor_sync(~0u, outA[t5], 2);
        outB[t5] += __shfl_xor_sync(~0u, outB[t5], 1);
        outB[t5] += __shfl_xor_sync(~0u, outB[t5], 2);
    }
    if (q == 0) {
#pragma unroll
        for (int h2 = 0; h2 < 2; ++h2) {
            int r = h2 ? rB : rA;
            float* o = h2 ? outB : outA;
            int p = p0 + r;
            int iu = g_iu[p], ju = g_ju[p];
            if (ju < vn) {
                int idx = iu*vn - iu*(iu+1)/2 + (ju - iu - 1);
#pragma unroll
                for (int t5 = 0; t5 < 10; ++t5)
                    out[(((size_t)b*5 + (t5 >> 1))*PP + idx)*2 + (t5 & 1)] = o[t5] + br2[t5];
            }
        }
    }
}

// ===================== host orchestration =====================================
extern "C" void kernel_launch(void* const* d_in, const int* in_sizes, int n_in,
                              void* d_out, int out_size) {
    const int*   edge_ids      = (const int*)  d_in[0];
    const float* node_features = (const float*)d_in[1];
    const int*   ev            = (const int*)  d_in[3];
    const float* emb           = (const float*)d_in[4];
    const float* Wl_e = (const float*)d_in[5];
    const float* Wl_w = (const float*)d_in[6];
    const float* Wl_v = (const float*)d_in[7];
    const float* bl1  = (const float*)d_in[8];
    const float* wl2  = (const float*)d_in[9];
    const float* bl2  = (const float*)d_in[10];
    const float* Wm_w = (const float*)d_in[11];
    const float* Wm_v = (const float*)d_in[12];
    const float* Wm_e = (const float*)d_in[13];
    const float* bm   = (const float*)d_in[14];
    const float* Wu_e = (const float*)d_in[15];
    const float* Wu_m = (const float*)d_in[16];
    const float* bu   = (const float*)d_in[17];
    const float* W_ih = (const float*)d_in[18];
    const float* W_hh = (const float*)d_in[19];
    const float* b_ih = (const float*)d_in[20];
    const float* b_hh = (const float*)d_in[21];
    const float* Wr1  = (const float*)d_in[22];
    const float* br1  = (const float*)d_in[23];
    const float* Wr2  = (const float*)d_in[24];
    const float* br2  = (const float*)d_in[25];

    cudaFuncSetAttribute(k_edge_mma,    cudaFuncAttributeMaxDynamicSharedMemorySize, EDGE_SMEM);
    cudaFuncSetAttribute(k_readout_mma, cudaFuncAttributeMaxDynamicSharedMemorySize, R2_SMEM);
    cudaFuncSetAttribute(k_rgemm_hp,    cudaFuncAttributeMaxDynamicSharedMemorySize, H2_SMEM);
    cudaFuncSetAttribute(k_rgemm_gig,   cudaFuncAttributeMaxDynamicSharedMemorySize, H2_SMEM);

    // launches: prep_w(0), prep_wr(1), hp(2), edge(3) — ncu captures index 3
    k_prep_w<<<896, 256>>>(Wl_e, Wm_e, Wu_e, Wu_m, Wl_w, Wl_v, Wm_w, Wm_v, W_ih, W_hh);
    k_prep_wr<<<256, 256>>>(Wr1);
    k_rgemm_hp<<<dim3(32, 8), 256, H2_SMEM>>>(node_features, bl1, bm, 1);

    for (int r = 0; r < RNDS; ++r) {
        if (r > 0)
            k_rgemm_hp<<<dim3(32, 8), 256, H2_SMEM>>>(node_features, bl1, bm, 0);
        k_edge_mma<<<BB*NN*2, 256, EDGE_SMEM>>>(wl2, bl2, bu, ev, edge_ids, emb, r == 0);
        k_reduce_ms<<<(BB*NN*CD/4 + 255)/256, 256>>>(ev);
        k_rgemm_gig<<<dim3(32, 6, 2), 256, H2_SMEM>>>(b_ih, b_hh);
        k_gru<<<(BB*NN*CD + 255)/256, 256>>>(ev);
    }

    cudaMemsetAsync(d_out, 0, (size_t)out_size * sizeof(float));
    k_readout_mma<<<dim3(PP/64, BB), 128, R2_SMEM>>>(br1, Wr2, br2, ev, (float*)d_out);
}